// round 8
// baseline (speedup 1.0000x reference)
#include <cuda_runtime.h>
#include <cuda_bf16.h>
#include <cstdint>

#define F 128
#define MAXN 50048
#define MAXE 1048576

// Device-global scratch. Never referenced from host; all atomics target these.
__device__ __align__(16) float g_h[(size_t)MAXN * F];     // GEMM out / gather src
__device__ __align__(16) float g_out1[(size_t)MAXN * F];  // layer-1 result
__device__ float g_dinv[MAXN];
__device__ int   g_deg[MAXN];
__device__ int   g_off[MAXN + 1];   // CSR row offsets (by dst)
__device__ int   g_cur[MAXN];       // build cursors
__device__ int   g_csr_src[MAXE];   // src node per CSR slot
__device__ float g_csr_norm[MAXE];  // dinv[src]*dinv[dst] per CSR slot
__device__ int   g_is64;

// ---------------------------------------------------------------------------
// init: zero degrees; block 0 also detects edge dtype IN PARALLEL
// (int64 little-endian => odd int32 words of first 64 entries are all zero)
// ---------------------------------------------------------------------------
__global__ void init_kernel(const int* __restrict__ ei32, int N) {
    int i = blockIdx.x * blockDim.x + threadIdx.x;
    if (i < N) g_deg[i] = 0;

    if (blockIdx.x == 0) {
        __shared__ int nz[64];
        int t = threadIdx.x;
        if (t < 64) nz[t] = (ei32[2 * t + 1] != 0);
        __syncthreads();
        if (t == 0) {
            int any = 0;
#pragma unroll
            for (int k = 0; k < 64; k++) any |= nz[k];
            g_is64 = any ? 0 : 1;
        }
    }
}

__device__ __forceinline__ int edge_at(const int* __restrict__ ei32,
                                       long long idx, int is64) {
    if (is64) return (int)__ldg(((const long long*)ei32) + idx);
    return __ldg(ei32 + idx);
}

// ---------------------------------------------------------------------------
// degree count
// ---------------------------------------------------------------------------
__global__ void count_deg_kernel(const int* __restrict__ ei, int E, int N) {
    int e = blockIdx.x * blockDim.x + threadIdx.x;
    if (e < E) {
        int is64 = g_is64;
        int dst = edge_at(ei, (long long)E + e, is64);
        if ((unsigned)dst < (unsigned)N)
            atomicAdd(&g_deg[dst], 1);
    }
}

// ---------------------------------------------------------------------------
// Single-block scan of g_deg -> g_off/g_cur, fused with dinv computation.
// ---------------------------------------------------------------------------
__global__ __launch_bounds__(1024)
void scan_dinv_kernel(int N) {
    __shared__ int sums[1024];
    int t = threadIdx.x;
    int chunk = (N + 1023) / 1024;
    int lo = t * chunk;
    int hi = min(lo + chunk, N);
    int s = 0;
    for (int i = lo; i < hi; i++) s += g_deg[i];
    sums[t] = s;
    __syncthreads();
    for (int d = 1; d < 1024; d <<= 1) {
        int v = (t >= d) ? sums[t - d] : 0;
        __syncthreads();
        sums[t] += v;
        __syncthreads();
    }
    int base = (t == 0) ? 0 : sums[t - 1];
    for (int i = lo; i < hi; i++) {
        int dg = g_deg[i];
        g_off[i] = base;
        g_cur[i] = base;
        g_dinv[i] = rsqrtf((float)(dg + 1));  // +1 = self-loop
        base += dg;
    }
    if (hi == N && lo <= N) g_off[N] = base;
}

__global__ void build_csr_kernel(const int* __restrict__ ei, int E, int N) {
    int e = blockIdx.x * blockDim.x + threadIdx.x;
    if (e >= E) return;
    int is64 = g_is64;
    int src = edge_at(ei, e, is64);
    int dst = edge_at(ei, (long long)E + e, is64);
    if ((unsigned)src >= (unsigned)N || (unsigned)dst >= (unsigned)N) return;
    int pos = atomicAdd(&g_cur[dst], 1);
    g_csr_src[pos] = src;
    g_csr_norm[pos] = g_dinv[src] * g_dinv[dst];
}

// ---------------------------------------------------------------------------
// TF32 tensor-core GEMM with gmem->reg prefetch pipelining.
// LAYER 0: g_h = Xext@W ; LAYER 1: g_h = relu(g_out1)@W
// BM=128, BN=128(=F), BK=32.  256 thr = 8 warps in 4x2; warp tile 32x64.
// ---------------------------------------------------------------------------
__device__ __forceinline__ uint32_t f2tf32(float f) {
    uint32_t r;
    asm("cvt.rna.tf32.f32 %0, %1;" : "=r"(r) : "f"(f));
    return r;
}

__device__ __forceinline__ void mma_tf32(float* c, const uint32_t* a,
                                         const uint32_t* b) {
    asm volatile(
        "mma.sync.aligned.m16n8k8.row.col.f32.tf32.tf32.f32 "
        "{%0,%1,%2,%3}, {%4,%5,%6,%7}, {%8,%9}, {%0,%1,%2,%3};\n"
        : "+f"(c[0]), "+f"(c[1]), "+f"(c[2]), "+f"(c[3])
        : "r"(a[0]), "r"(a[1]), "r"(a[2]), "r"(a[3]), "r"(b[0]), "r"(b[1]));
}

template <int LAYER>
__global__ __launch_bounds__(256)
void gemm_kernel(const float* __restrict__ Xext, const float* __restrict__ W,
                 int N) {
    // pads: 33 % 32 == 1 and 136 % 32 == 8 -> conflict-free fragment loads
    __shared__ uint32_t As[128][33];
    __shared__ uint32_t Bs[32][136];

    const float* X = (LAYER == 0) ? Xext : g_out1;

    const int tid = threadIdx.x;
    const int wid = tid >> 5;
    const int lane = tid & 31;
    const int wm = wid & 3;            // 0..3 -> 32-row band
    const int wn = wid >> 2;           // 0..1 -> 64-col band
    const int row0 = blockIdx.x * 128;

    // per-thread gmem staging regs
    float4 av[4], bv[4];
    const int a_r = tid >> 3;               // A: 8 float4 per row
    const int a_c4 = (tid & 7) * 4;
    const int a_row = row0 + a_r;
    const int b_r = tid >> 5;               // B: 32 float4 per row
    const int b_c4 = (tid & 31) * 4;

    auto load_slab = [&](int kc) {
        const int k0 = kc * 32;
#pragma unroll
        for (int l = 0; l < 4; l++) {
            int grow = a_row + l * 32;      // +256 threads/8 = 32 rows
            float4 v = make_float4(0.f, 0.f, 0.f, 0.f);
            if (grow < N) v = *(const float4*)(X + (size_t)grow * F + k0 + a_c4);
            av[l] = v;
        }
#pragma unroll
        for (int l = 0; l < 4; l++) {
            int r = b_r + l * 8;            // +256 threads/32 = 8 rows
            bv[l] = *(const float4*)(W + (size_t)(k0 + r) * F + b_c4);
        }
    };

    float acc[2][8][4];
#pragma unroll
    for (int mt = 0; mt < 2; mt++)
#pragma unroll
        for (int j = 0; j < 8; j++)
#pragma unroll
            for (int q = 0; q < 4; q++) acc[mt][j][q] = 0.0f;

    load_slab(0);

    for (int kc = 0; kc < 4; kc++) {
        // stage regs -> smem (with relu/cvt)
#pragma unroll
        for (int l = 0; l < 4; l++) {
            float4 v = av[l];
            if (LAYER == 1) {
                v.x = fmaxf(v.x, 0.f); v.y = fmaxf(v.y, 0.f);
                v.z = fmaxf(v.z, 0.f); v.w = fmaxf(v.w, 0.f);
            }
            int r = a_r + l * 32;
            As[r][a_c4] = f2tf32(v.x); As[r][a_c4 + 1] = f2tf32(v.y);
            As[r][a_c4 + 2] = f2tf32(v.z); As[r][a_c4 + 3] = f2tf32(v.w);
        }
#pragma unroll
        for (int l = 0; l < 4; l++) {
            float4 v = bv[l];
            int r = b_r + l * 8;
            Bs[r][b_c4] = f2tf32(v.x); Bs[r][b_c4 + 1] = f2tf32(v.y);
            Bs[r][b_c4 + 2] = f2tf32(v.z); Bs[r][b_c4 + 3] = f2tf32(v.w);
        }
        __syncthreads();

        if (kc < 3) load_slab(kc + 1);   // overlap gmem latency with MMAs

#pragma unroll
        for (int ks = 0; ks < 4; ks++) {
            const int kk = ks * 8;
            const int g = lane >> 2;     // 0..7
            const int r4 = lane & 3;     // 0..3
            uint32_t a[2][4];
#pragma unroll
            for (int mt = 0; mt < 2; mt++) {
                int ar = wm * 32 + mt * 16 + g;
                a[mt][0] = As[ar][kk + r4];
                a[mt][1] = As[ar + 8][kk + r4];
                a[mt][2] = As[ar][kk + r4 + 4];
                a[mt][3] = As[ar + 8][kk + r4 + 4];
            }
            uint32_t b[8][2];
#pragma unroll
            for (int j = 0; j < 8; j++) {
                int bc = wn * 64 + j * 8 + g;
                b[j][0] = Bs[kk + r4][bc];
                b[j][1] = Bs[kk + r4 + 4][bc];
            }
#pragma unroll
            for (int mt = 0; mt < 2; mt++)
#pragma unroll
                for (int j = 0; j < 8; j++)
                    mma_tf32(acc[mt][j], a[mt], b[j]);
        }
        __syncthreads();
    }

    // epilogue
    const int g = lane >> 2;
    const int r4 = lane & 3;
#pragma unroll
    for (int mt = 0; mt < 2; mt++) {
        int row = row0 + wm * 32 + mt * 16 + g;
#pragma unroll
        for (int j = 0; j < 8; j++) {
            int col = wn * 64 + j * 8 + r4 * 2;
            if (row < N)
                *(float2*)(g_h + (size_t)row * F + col) =
                    make_float2(acc[mt][j][0], acc[mt][j][1]);
            if (row + 8 < N)
                *(float2*)(g_h + (size_t)(row + 8) * F + col) =
                    make_float2(acc[mt][j][2], acc[mt][j][3]);
        }
    }
}

// ---------------------------------------------------------------------------
// Gather aggregation: one warp per dst node, zero atomics.
//   out[n] = bias + g_h[n]*dinv[n]^2 + sum_{e in CSR[n]} g_h[src_e]*norm_e
// ---------------------------------------------------------------------------
template <int LAYER>
__global__ __launch_bounds__(256)
void gather_kernel(const float* __restrict__ bias, float* __restrict__ out_ext,
                   int N) {
    int w = (blockIdx.x * blockDim.x + threadIdx.x) >> 5;
    int lane = threadIdx.x & 31;
    if (w >= N) return;

    const int c = lane * 4;
    const int off = g_off[w];
    const int end = g_off[w + 1];

    float d = g_dinv[w];
    float d2 = d * d;
    float4 hv = *(const float4*)(g_h + (size_t)w * F + c);
    float4 bv = *(const float4*)(bias + c);
    float4 acc = make_float4(bv.x + hv.x * d2, bv.y + hv.y * d2,
                             bv.z + hv.z * d2, bv.w + hv.w * d2);

    int e = off;
    for (; e + 3 < end; e += 4) {
        int s0 = g_csr_src[e], s1 = g_csr_src[e + 1];
        int s2 = g_csr_src[e + 2], s3 = g_csr_src[e + 3];
        float n0 = g_csr_norm[e], n1 = g_csr_norm[e + 1];
        float n2 = g_csr_norm[e + 2], n3 = g_csr_norm[e + 3];
        float4 v0 = *(const float4*)(g_h + (size_t)s0 * F + c);
        float4 v1 = *(const float4*)(g_h + (size_t)s1 * F + c);
        float4 v2 = *(const float4*)(g_h + (size_t)s2 * F + c);
        float4 v3 = *(const float4*)(g_h + (size_t)s3 * F + c);
        acc.x += v0.x * n0; acc.y += v0.y * n0; acc.z += v0.z * n0; acc.w += v0.w * n0;
        acc.x += v1.x * n1; acc.y += v1.y * n1; acc.z += v1.z * n1; acc.w += v1.w * n1;
        acc.x += v2.x * n2; acc.y += v2.y * n2; acc.z += v2.z * n2; acc.w += v2.w * n2;
        acc.x += v3.x * n3; acc.y += v3.y * n3; acc.z += v3.z * n3; acc.w += v3.w * n3;
    }
    for (; e < end; e++) {
        int s0 = g_csr_src[e];
        float n0 = g_csr_norm[e];
        float4 v0 = *(const float4*)(g_h + (size_t)s0 * F + c);
        acc.x += v0.x * n0; acc.y += v0.y * n0; acc.z += v0.z * n0; acc.w += v0.w * n0;
    }

    if (LAYER == 1) {
        acc.x = fmaxf(acc.x, 0.f); acc.y = fmaxf(acc.y, 0.f);
        acc.z = fmaxf(acc.z, 0.f); acc.w = fmaxf(acc.w, 0.f);
        *(float4*)(out_ext + (size_t)w * F + c) = acc;   // plain STG to d_out
    } else {
        *(float4*)(g_out1 + (size_t)w * F + c) = acc;
    }
}

extern "C" void kernel_launch(void* const* d_in, const int* in_sizes, int n_in,
                              void* d_out, int out_size) {
    const float* x = (const float*)d_in[0];
    const int* ei = (const int*)d_in[1];   // int32 or int64, detected on device
    const float* W1 = (const float*)d_in[2];
    const float* b1 = (const float*)d_in[3];
    const float* W2 = (const float*)d_in[4];
    const float* b2 = (const float*)d_in[5];
    float* out = (float*)d_out;

    int N = in_sizes[0] / F;
    int E = in_sizes[1] / 2;

    // --- CSR build (shared by both layers) ---
    init_kernel<<<(N + 255) / 256, 256>>>(ei, N);
    count_deg_kernel<<<(E + 255) / 256, 256>>>(ei, E, N);
    scan_dinv_kernel<<<1, 1024>>>(N);
    build_csr_kernel<<<(E + 255) / 256, 256>>>(ei, E, N);

    int gemm_grid = (N + 127) / 128;
    int gath_grid = (N * 32 + 255) / 256;

    // --- layer 1 ---
    gemm_kernel<0><<<gemm_grid, 256>>>(x, W1, N);
    gather_kernel<0><<<gath_grid, 256>>>(b1, nullptr, N);

    // --- layer 2 (relu fused into gather epilogue, direct store to d_out) ---
    gemm_kernel<1><<<gemm_grid, 256>>>(nullptr, W2, N);
    gather_kernel<1><<<gath_grid, 256>>>(b2, out, N);
}

// round 9
// speedup vs baseline: 1.0398x; 1.0398x over previous
#include <cuda_runtime.h>
#include <cuda_bf16.h>
#include <cstdint>

#define F 128
#define MAXN 50048
#define MAXE 1048576

// Device-global scratch. Never referenced from host; all atomics target these.
__device__ __align__(16) float g_h[(size_t)MAXN * F];     // hs = h*dinv (gather src)
__device__ __align__(16) float g_out1[(size_t)MAXN * F];  // relu(layer-1) result
__device__ float g_dinv[MAXN];
__device__ int   g_deg[MAXN];
__device__ int   g_off[MAXN + 1];   // CSR row offsets (by dst)
__device__ int   g_cur[MAXN];       // build cursors
__device__ int   g_csr_src[MAXE];   // src node per CSR slot
__device__ int   g_is64;

// ---------------------------------------------------------------------------
// init: zero degrees; block 0 detects edge dtype in parallel
// (int64 little-endian => odd int32 words of first 64 entries are all zero)
// ---------------------------------------------------------------------------
__global__ void init_kernel(const int* __restrict__ ei32, int N) {
    int i = blockIdx.x * blockDim.x + threadIdx.x;
    if (i < N) g_deg[i] = 0;

    if (blockIdx.x == 0) {
        __shared__ int nz[64];
        int t = threadIdx.x;
        if (t < 64) nz[t] = (ei32[2 * t + 1] != 0);
        __syncthreads();
        if (t == 0) {
            int any = 0;
#pragma unroll
            for (int k = 0; k < 64; k++) any |= nz[k];
            g_is64 = any ? 0 : 1;
        }
    }
}

__device__ __forceinline__ int edge_at(const int* __restrict__ ei32,
                                       long long idx, int is64) {
    if (is64) return (int)__ldg(((const long long*)ei32) + idx);
    return __ldg(ei32 + idx);
}

// ---------------------------------------------------------------------------
// degree count
// ---------------------------------------------------------------------------
__global__ void count_deg_kernel(const int* __restrict__ ei, int E, int N) {
    int e = blockIdx.x * blockDim.x + threadIdx.x;
    if (e < E) {
        int is64 = g_is64;
        int dst = edge_at(ei, (long long)E + e, is64);
        if ((unsigned)dst < (unsigned)N)
            atomicAdd(&g_deg[dst], 1);
    }
}

// ---------------------------------------------------------------------------
// Single-block scan of g_deg -> g_off/g_cur, fused with dinv computation.
// ---------------------------------------------------------------------------
__global__ __launch_bounds__(1024)
void scan_dinv_kernel(int N) {
    __shared__ int sums[1024];
    int t = threadIdx.x;
    int chunk = (N + 1023) / 1024;
    int lo = t * chunk;
    int hi = min(lo + chunk, N);
    int s = 0;
    for (int i = lo; i < hi; i++) s += g_deg[i];
    sums[t] = s;
    __syncthreads();
    for (int d = 1; d < 1024; d <<= 1) {
        int v = (t >= d) ? sums[t - d] : 0;
        __syncthreads();
        sums[t] += v;
        __syncthreads();
    }
    int base = (t == 0) ? 0 : sums[t - 1];
    for (int i = lo; i < hi; i++) {
        int dg = g_deg[i];
        g_off[i] = base;
        g_cur[i] = base;
        g_dinv[i] = rsqrtf((float)(dg + 1));  // +1 = self-loop
        base += dg;
    }
    if (hi == N && lo <= N) g_off[N] = base;
}

// CSR placement: only src indices — norms are factored out algebraically.
__global__ void build_csr_kernel(const int* __restrict__ ei, int E, int N) {
    int e = blockIdx.x * blockDim.x + threadIdx.x;
    if (e >= E) return;
    int is64 = g_is64;
    int src = edge_at(ei, e, is64);
    int dst = edge_at(ei, (long long)E + e, is64);
    if ((unsigned)src >= (unsigned)N || (unsigned)dst >= (unsigned)N) return;
    int pos = atomicAdd(&g_cur[dst], 1);
    g_csr_src[pos] = src;
}

// ---------------------------------------------------------------------------
// TF32 tensor-core GEMM (R6 form — no reg prefetch; 2 CTAs/SM).
// LAYER 0: hs = (Xext@W)*dinv ; LAYER 1: hs = (g_out1@W)*dinv
// (g_out1 already holds relu'd values, so no relu on the A-load path.)
// BM=128, BN=128(=F), BK=32.  256 thr = 8 warps in 4x2; warp tile 32x64.
// ---------------------------------------------------------------------------
__device__ __forceinline__ uint32_t f2tf32(float f) {
    uint32_t r;
    asm("cvt.rna.tf32.f32 %0, %1;" : "=r"(r) : "f"(f));
    return r;
}

__device__ __forceinline__ void mma_tf32(float* c, const uint32_t* a,
                                         const uint32_t* b) {
    asm volatile(
        "mma.sync.aligned.m16n8k8.row.col.f32.tf32.tf32.f32 "
        "{%0,%1,%2,%3}, {%4,%5,%6,%7}, {%8,%9}, {%0,%1,%2,%3};\n"
        : "+f"(c[0]), "+f"(c[1]), "+f"(c[2]), "+f"(c[3])
        : "r"(a[0]), "r"(a[1]), "r"(a[2]), "r"(a[3]), "r"(b[0]), "r"(b[1]));
}

template <int LAYER>
__global__ __launch_bounds__(256)
void gemm_kernel(const float* __restrict__ Xext, const float* __restrict__ W,
                 int N) {
    // pads: 33 % 32 == 1 and 136 % 32 == 8 -> conflict-free fragment loads
    __shared__ uint32_t As[128][33];
    __shared__ uint32_t Bs[32][136];

    const float* X = (LAYER == 0) ? Xext : g_out1;

    const int tid = threadIdx.x;
    const int wid = tid >> 5;
    const int lane = tid & 31;
    const int wm = wid & 3;            // 0..3 -> 32-row band
    const int wn = wid >> 2;           // 0..1 -> 64-col band
    const int row0 = blockIdx.x * 128;

    float acc[2][8][4];
#pragma unroll
    for (int mt = 0; mt < 2; mt++)
#pragma unroll
        for (int j = 0; j < 8; j++)
#pragma unroll
            for (int q = 0; q < 4; q++) acc[mt][j][q] = 0.0f;

    for (int kc = 0; kc < 4; kc++) {
        const int k0 = kc * 32;
        // --- A tile: 128x32 floats = 1024 float4 = 256 thr * 4 ---
#pragma unroll
        for (int l = 0; l < 4; l++) {
            int f4 = tid + l * 256;
            int r = f4 >> 3;
            int c4 = (f4 & 7) * 4;
            int grow = row0 + r;
            float4 v = make_float4(0.f, 0.f, 0.f, 0.f);
            if (grow < N) v = *(const float4*)(X + (size_t)grow * F + k0 + c4);
            As[r][c4] = f2tf32(v.x); As[r][c4 + 1] = f2tf32(v.y);
            As[r][c4 + 2] = f2tf32(v.z); As[r][c4 + 3] = f2tf32(v.w);
        }
        // --- B tile: 32x128 floats = 1024 float4 = 256 thr * 4 ---
#pragma unroll
        for (int l = 0; l < 4; l++) {
            int f4 = tid + l * 256;
            int r = f4 >> 5;
            int c4 = (f4 & 31) * 4;
            float4 v = *(const float4*)(W + (size_t)(k0 + r) * F + c4);
            Bs[r][c4] = f2tf32(v.x); Bs[r][c4 + 1] = f2tf32(v.y);
            Bs[r][c4 + 2] = f2tf32(v.z); Bs[r][c4 + 3] = f2tf32(v.w);
        }
        __syncthreads();

#pragma unroll
        for (int ks = 0; ks < 4; ks++) {
            const int kk = ks * 8;
            const int g = lane >> 2;
            const int r4 = lane & 3;
            uint32_t a[2][4];
#pragma unroll
            for (int mt = 0; mt < 2; mt++) {
                int ar = wm * 32 + mt * 16 + g;
                a[mt][0] = As[ar][kk + r4];
                a[mt][1] = As[ar + 8][kk + r4];
                a[mt][2] = As[ar][kk + r4 + 4];
                a[mt][3] = As[ar + 8][kk + r4 + 4];
            }
            uint32_t b[8][2];
#pragma unroll
            for (int j = 0; j < 8; j++) {
                int bc = wn * 64 + j * 8 + g;
                b[j][0] = Bs[kk + r4][bc];
                b[j][1] = Bs[kk + r4 + 4][bc];
            }
#pragma unroll
            for (int mt = 0; mt < 2; mt++)
#pragma unroll
                for (int j = 0; j < 8; j++)
                    mma_tf32(acc[mt][j], a[mt], b[j]);
        }
        __syncthreads();
    }

    // epilogue: scale by dinv[row] -> store hs = h*dinv
    const int g = lane >> 2;
    const int r4 = lane & 3;
#pragma unroll
    for (int mt = 0; mt < 2; mt++) {
        int row = row0 + wm * 32 + mt * 16 + g;
        float d0 = (row < N) ? g_dinv[row] : 0.f;
        float d1 = (row + 8 < N) ? g_dinv[row + 8] : 0.f;
#pragma unroll
        for (int j = 0; j < 8; j++) {
            int col = wn * 64 + j * 8 + r4 * 2;
            if (row < N)
                *(float2*)(g_h + (size_t)row * F + col) =
                    make_float2(acc[mt][j][0] * d0, acc[mt][j][1] * d0);
            if (row + 8 < N)
                *(float2*)(g_h + (size_t)(row + 8) * F + col) =
                    make_float2(acc[mt][j][2] * d1, acc[mt][j][3] * d1);
        }
    }
}

// ---------------------------------------------------------------------------
// Gather: one warp per dst node, zero atomics, no per-edge norms:
//   out[n] = bias + dinv[n] * (hs[n] + sum_{e in CSR[n]} hs[src_e])
// LAYER 0 stores relu(out) into g_out1; LAYER 1 stores relu(out) into d_out.
// ---------------------------------------------------------------------------
template <int LAYER>
__global__ __launch_bounds__(256)
void gather_kernel(const float* __restrict__ bias, float* __restrict__ out_ext,
                   int N) {
    int w = (blockIdx.x * blockDim.x + threadIdx.x) >> 5;
    int lane = threadIdx.x & 31;
    if (w >= N) return;

    const int c = lane * 4;
    const int off = g_off[w];
    const int end = g_off[w + 1];

    float4 acc = *(const float4*)(g_h + (size_t)w * F + c);  // hs[n] self term

    int e = off;
    for (; e + 3 < end; e += 4) {
        int s0 = g_csr_src[e], s1 = g_csr_src[e + 1];
        int s2 = g_csr_src[e + 2], s3 = g_csr_src[e + 3];
        float4 v0 = *(const float4*)(g_h + (size_t)s0 * F + c);
        float4 v1 = *(const float4*)(g_h + (size_t)s1 * F + c);
        float4 v2 = *(const float4*)(g_h + (size_t)s2 * F + c);
        float4 v3 = *(const float4*)(g_h + (size_t)s3 * F + c);
        acc.x += v0.x; acc.y += v0.y; acc.z += v0.z; acc.w += v0.w;
        acc.x += v1.x; acc.y += v1.y; acc.z += v1.z; acc.w += v1.w;
        acc.x += v2.x; acc.y += v2.y; acc.z += v2.z; acc.w += v2.w;
        acc.x += v3.x; acc.y += v3.y; acc.z += v3.z; acc.w += v3.w;
    }
    for (; e < end; e++) {
        int s0 = g_csr_src[e];
        float4 v0 = *(const float4*)(g_h + (size_t)s0 * F + c);
        acc.x += v0.x; acc.y += v0.y; acc.z += v0.z; acc.w += v0.w;
    }

    float d = g_dinv[w];
    float4 bv = *(const float4*)(bias + c);
    float4 r = make_float4(fmaxf(bv.x + d * acc.x, 0.f),
                           fmaxf(bv.y + d * acc.y, 0.f),
                           fmaxf(bv.z + d * acc.z, 0.f),
                           fmaxf(bv.w + d * acc.w, 0.f));

    if (LAYER == 1)
        *(float4*)(out_ext + (size_t)w * F + c) = r;   // plain STG to d_out
    else
        *(float4*)(g_out1 + (size_t)w * F + c) = r;    // already relu'd
}

extern "C" void kernel_launch(void* const* d_in, const int* in_sizes, int n_in,
                              void* d_out, int out_size) {
    const float* x = (const float*)d_in[0];
    const int* ei = (const int*)d_in[1];   // int32 or int64, detected on device
    const float* W1 = (const float*)d_in[2];
    const float* b1 = (const float*)d_in[3];
    const float* W2 = (const float*)d_in[4];
    const float* b2 = (const float*)d_in[5];
    float* out = (float*)d_out;

    int N = in_sizes[0] / F;
    int E = in_sizes[1] / 2;

    // --- CSR build (shared by both layers) ---
    init_kernel<<<(N + 255) / 256, 256>>>(ei, N);
    count_deg_kernel<<<(E + 255) / 256, 256>>>(ei, E, N);
    scan_dinv_kernel<<<1, 1024>>>(N);
    build_csr_kernel<<<(E + 255) / 256, 256>>>(ei, E, N);

    int gemm_grid = (N + 127) / 128;
    int gath_grid = (N * 32 + 255) / 256;

    // --- layer 1 ---
    gemm_kernel<0><<<gemm_grid, 256>>>(x, W1, N);
    gather_kernel<0><<<gath_grid, 256>>>(b1, nullptr, N);

    // --- layer 2 (direct store to d_out) ---
    gemm_kernel<1><<<gemm_grid, 256>>>(nullptr, W2, N);
    gather_kernel<1><<<gath_grid, 256>>>(b2, out, N);
}